// round 13
// baseline (speedup 1.0000x reference)
#include <cuda_runtime.h>
#include <math.h>
#include <stdint.h>

#define BATCH   32
#define TLEN    2048
#define HE      1024
#define NCHUNK  13                // 416 CTAs = one wave at occ 3 (148 SMs -> 444)
#define CBASE   (TLEN / NCHUNK)   // 157
#define CREM    (TLEN - CBASE * NCHUNK) // 7 chunks get one extra row
#define THREADS 256
#define WARPS   (THREADS / 32)

// Cross-CTA partials (allocation-free scratch)
__device__ float g_pz[BATCH * NCHUNK];
__device__ float g_pacc[BATCH * NCHUNK * HE];
__device__ unsigned int g_ticket[BATCH];   // zero-init; self-resetting

__global__ __launch_bounds__(THREADS, 3)
void attn_fused_kernel(const float* __restrict__ hidden,   // (2,32,1024)
                       const float* __restrict__ enc,      // (32,2048,1024)
                       const float* __restrict__ mask,     // (32,2048)
                       const float* __restrict__ attn_w,   // (3072,)
                       const float* __restrict__ attn_b,   // (1,)
                       float* __restrict__ out)            // (32,1024)
{
    __shared__ float s_we[HE];             // w_e staged in smem (frees 32 regs)
    __shared__ float s_acc[WARPS * HE];    // 32KB warp-partial reduce
    __shared__ float s_z[WARPS];
    __shared__ float s_red[WARPS];
    __shared__ float s_hb;
    __shared__ unsigned s_ticket;

    const int tid   = threadIdx.x;
    const int lane  = tid & 31;
    const int warp  = tid >> 5;
    const int b     = blockIdx.x / NCHUNK;
    const int chunk = blockIdx.x % NCHUNK;

    const int t_begin = chunk * CBASE + min(chunk, CREM);
    const int t_end   = t_begin + CBASE + (chunk < CREM ? 1 : 0);

    // ---- stage w_e into smem ----
    for (int i = tid; i < HE; i += THREADS) s_we[i] = attn_w[2048 + i];

    // ---- hb = hid_flat[b].w_h + bias ----
    float hsum = 0.f;
    for (int i = tid; i < 2048; i += THREADS) {
        int j = i >> 10, k = i & 1023;
        hsum += hidden[(size_t)j * BATCH * HE + (size_t)b * HE + k] * attn_w[i];
    }
    #pragma unroll
    for (int o = 16; o; o >>= 1) hsum += __shfl_xor_sync(0xffffffffu, hsum, o);
    if (lane == 0) s_red[warp] = hsum;
    __syncthreads();
    if (tid == 0) {
        float s = 0.f;
        #pragma unroll
        for (int w = 0; w < WARPS; w++) s += s_red[w];
        s_hb = s + attn_b[0];
    }
    __syncthreads();
    const float hb = s_hb;

    const float*  mrow = mask + (size_t)b * TLEN;
    const float4* encb = (const float4*)(enc + (size_t)b * TLEN * HE);
    const float4* wsm  = (const float4*)s_we;

    float z = 0.f;
    float4 acc[8];
    #pragma unroll
    for (int i = 0; i < 8; i++) acc[i] = make_float4(0.f, 0.f, 0.f, 0.f);

    // ---- mainloop: warp owns a row; no barriers; single row buffer ----
    for (int t = t_begin + warp; t < t_end; t += WARPS) {
        const float mk = mrow[t];                      // off critical path
        const float4* row4 = encb + (size_t)t * (HE / 4);

        float4 v[8];
        #pragma unroll
        for (int i = 0; i < 8; i++) v[i] = row4[lane + 32 * i];  // 8 LDG.128

        float e = 0.f;
        #pragma unroll
        for (int i = 0; i < 8; i++) {
            float4 w = wsm[lane + 32 * i];
            e += v[i].x * w.x + v[i].y * w.y + v[i].z * w.z + v[i].w * w.w;
        }
        #pragma unroll
        for (int o = 16; o; o >>= 1) e += __shfl_xor_sync(0xffffffffu, e, o);

        // energies*mask before softmax; exp without max (|e|~O(6)); *mask after
        const float wgt = __expf((e + hb) * mk) * mk;
        z += wgt;
        #pragma unroll
        for (int i = 0; i < 8; i++) {
            acc[i].x += wgt * v[i].x; acc[i].y += wgt * v[i].y;
            acc[i].z += wgt * v[i].z; acc[i].w += wgt * v[i].w;
        }
    }

    // ---- CTA reduction of 8 warp partials ----
    #pragma unroll
    for (int i = 0; i < 8; i++)
        ((float4*)s_acc)[warp * (HE / 4) + i * 32 + lane] = acc[i];
    if (lane == 0) s_z[warp] = z;
    __syncthreads();

    float4 o = make_float4(0.f, 0.f, 0.f, 0.f);
    #pragma unroll
    for (int w = 0; w < WARPS; w++) {
        float4 a = ((const float4*)s_acc)[w * (HE / 4) + tid];
        o.x += a.x; o.y += a.y; o.z += a.z; o.w += a.w;
    }
    float zc = 0.f;
    if (tid == 0) {
        #pragma unroll
        for (int w = 0; w < WARPS; w++) zc += s_z[w];
    }

    // ---- write partials; ticketed last-CTA combine per batch ----
    const int pidx = b * NCHUNK + chunk;
    if (tid == 0) g_pz[pidx] = zc;
    ((float4*)(g_pacc + (size_t)pidx * HE))[tid] = o;
    __threadfence();
    __syncthreads();
    if (tid == 0) s_ticket = atomicAdd(&g_ticket[b], 1u);
    __syncthreads();

    if (s_ticket == NCHUNK - 1) {
        __threadfence();   // acquire peer partials

        float Z = 0.f;
        #pragma unroll
        for (int c = 0; c < NCHUNK; c++) Z += g_pz[b * NCHUNK + c];
        const float inv = 1.f / Z;

        float4 r = make_float4(0.f, 0.f, 0.f, 0.f);
        #pragma unroll
        for (int c = 0; c < NCHUNK; c++) {
            float4 a = ((const float4*)(g_pacc + (size_t)(b * NCHUNK + c) * HE))[tid];
            r.x += a.x; r.y += a.y; r.z += a.z; r.w += a.w;
        }
        r.x *= inv; r.y *= inv; r.z *= inv; r.w *= inv;
        ((float4*)(out + (size_t)b * HE))[tid] = r;

        if (tid == 0) g_ticket[b] = 0;   // self-reset for next graph replay
    }
}

extern "C" void kernel_launch(void* const* d_in, const int* in_sizes, int n_in,
                              void* d_out, int out_size)
{
    const float* hidden = (const float*)d_in[0];  // (2,32,1024)
    const float* enc    = (const float*)d_in[1];  // (32,2048,1024)
    const float* mask   = (const float*)d_in[2];  // (32,2048)
    const float* attn_w = (const float*)d_in[3];  // (3072,)
    const float* attn_b = (const float*)d_in[4];  // (1,)
    float* out = (float*)d_out;                   // (32,1024)

    attn_fused_kernel<<<BATCH * NCHUNK, THREADS>>>(
        hidden, enc, mask, attn_w, attn_b, out);
}

// round 14
// speedup vs baseline: 1.2248x; 1.2248x over previous
#include <cuda_runtime.h>
#include <math.h>
#include <stdint.h>

#define BATCH   32
#define TLEN    2048
#define HE      1024
#define NCHUNK  18                // 576 CTAs: ~3.9 sequential CTAs/SM absorbs L1tex-queue spread
#define CBASE   (TLEN / NCHUNK)   // 113
#define CREM    (TLEN - CBASE * NCHUNK) // 14 chunks get one extra row
#define THREADS 256
#define WARPS   (THREADS / 32)

// Cross-CTA partials (allocation-free scratch)
__device__ float g_pz[BATCH * NCHUNK];
__device__ float g_pacc[BATCH * NCHUNK * HE];
__device__ unsigned int g_ticket[BATCH];   // zero-init; self-resetting

__global__ __launch_bounds__(THREADS, 2)
void attn_fused_kernel(const float* __restrict__ hidden,   // (2,32,1024)
                       const float* __restrict__ enc,      // (32,2048,1024)
                       const float* __restrict__ mask,     // (32,2048)
                       const float* __restrict__ attn_w,   // (3072,)
                       const float* __restrict__ attn_b,   // (1,)
                       float* __restrict__ out)            // (32,1024)
{
    __shared__ float s_acc[WARPS * HE];    // 32KB warp-partial reduce
    __shared__ float s_z[WARPS];
    __shared__ float s_red[WARPS];
    __shared__ float s_hb;
    __shared__ unsigned s_ticket;

    const int tid   = threadIdx.x;
    const int lane  = tid & 31;
    const int warp  = tid >> 5;
    const int b     = blockIdx.x / NCHUNK;
    const int chunk = blockIdx.x % NCHUNK;

    const int t_begin = chunk * CBASE + min(chunk, CREM);
    const int t_end   = t_begin + CBASE + (chunk < CREM ? 1 : 0);

    // ---- w_e register-resident: lane l holds float4 slots l+32i ----
    const float4* w4g = (const float4*)attn_w;   // attn_w[2048..3071] -> float4[512..767]
    float4 we[8];
    #pragma unroll
    for (int i = 0; i < 8; i++) we[i] = __ldg(&w4g[512 + lane + 32 * i]);

    // ---- hb = hid_flat[b].w_h + bias ----
    float hsum = 0.f;
    for (int i = tid; i < 2048; i += THREADS) {
        int j = i >> 10, k = i & 1023;
        hsum += hidden[(size_t)j * BATCH * HE + (size_t)b * HE + k] * attn_w[i];
    }
    #pragma unroll
    for (int o = 16; o; o >>= 1) hsum += __shfl_xor_sync(0xffffffffu, hsum, o);
    if (lane == 0) s_red[warp] = hsum;
    __syncthreads();
    if (tid == 0) {
        float s = 0.f;
        #pragma unroll
        for (int w = 0; w < WARPS; w++) s += s_red[w];
        s_hb = s + attn_b[0];
    }
    __syncthreads();
    const float hb = s_hb;

    // ---- mainloop: warp owns a row; no barriers; w_e in registers ----
    const float*  mrow = mask + (size_t)b * TLEN;
    const float4* encb = (const float4*)(enc + (size_t)b * TLEN * HE);

    float z = 0.f;
    float4 acc[8];
    #pragma unroll
    for (int i = 0; i < 8; i++) acc[i] = make_float4(0.f, 0.f, 0.f, 0.f);

    for (int t = t_begin + warp; t < t_end; t += WARPS) {
        const float mk = __ldg(&mrow[t]);              // off critical path
        const float4* row4 = encb + (size_t)t * (HE / 4);

        float4 v[8];
        #pragma unroll
        for (int i = 0; i < 8; i++) v[i] = row4[lane + 32 * i];   // 8 LDG.128 in flight

        float e = 0.f;
        #pragma unroll
        for (int i = 0; i < 8; i++)
            e += v[i].x * we[i].x + v[i].y * we[i].y + v[i].z * we[i].z + v[i].w * we[i].w;
        #pragma unroll
        for (int o = 16; o; o >>= 1) e += __shfl_xor_sync(0xffffffffu, e, o);

        // energies*mask before softmax; exp without max (|e|~O(6)); *mask after
        const float w = __expf((e + hb) * mk) * mk;
        z += w;
        #pragma unroll
        for (int i = 0; i < 8; i++) {
            acc[i].x += w * v[i].x; acc[i].y += w * v[i].y;
            acc[i].z += w * v[i].z; acc[i].w += w * v[i].w;
        }
    }

    // ---- CTA reduction of 8 warp partials ----
    #pragma unroll
    for (int i = 0; i < 8; i++)
        ((float4*)s_acc)[warp * (HE / 4) + i * 32 + lane] = acc[i];
    if (lane == 0) s_z[warp] = z;
    __syncthreads();

    float4 o = make_float4(0.f, 0.f, 0.f, 0.f);
    #pragma unroll
    for (int w = 0; w < WARPS; w++) {
        float4 a = ((const float4*)s_acc)[w * (HE / 4) + tid];
        o.x += a.x; o.y += a.y; o.z += a.z; o.w += a.w;
    }
    float zc = 0.f;
    if (tid == 0) {
        #pragma unroll
        for (int w = 0; w < WARPS; w++) zc += s_z[w];
    }

    // ---- write partials; ticketed last-CTA combine per batch ----
    const int pidx = b * NCHUNK + chunk;
    if (tid == 0) g_pz[pidx] = zc;
    ((float4*)(g_pacc + (size_t)pidx * HE))[tid] = o;
    __threadfence();
    __syncthreads();
    if (tid == 0) s_ticket = atomicAdd(&g_ticket[b], 1u);
    __syncthreads();

    if (s_ticket == NCHUNK - 1) {
        __threadfence();   // acquire peer partials

        float Z = 0.f;
        #pragma unroll
        for (int c = 0; c < NCHUNK; c++) Z += g_pz[b * NCHUNK + c];
        const float inv = 1.f / Z;

        float4 r = make_float4(0.f, 0.f, 0.f, 0.f);
        #pragma unroll
        for (int c = 0; c < NCHUNK; c++) {
            float4 a = ((const float4*)(g_pacc + (size_t)(b * NCHUNK + c) * HE))[tid];
            r.x += a.x; r.y += a.y; r.z += a.z; r.w += a.w;
        }
        r.x *= inv; r.y *= inv; r.z *= inv; r.w *= inv;
        ((float4*)(out + (size_t)b * HE))[tid] = r;

        if (tid == 0) g_ticket[b] = 0;   // self-reset for next graph replay
    }
}

extern "C" void kernel_launch(void* const* d_in, const int* in_sizes, int n_in,
                              void* d_out, int out_size)
{
    const float* hidden = (const float*)d_in[0];  // (2,32,1024)
    const float* enc    = (const float*)d_in[1];  // (32,2048,1024)
    const float* mask   = (const float*)d_in[2];  // (32,2048)
    const float* attn_w = (const float*)d_in[3];  // (3072,)
    const float* attn_b = (const float*)d_in[4];  // (1,)
    float* out = (float*)d_out;                   // (32,1024)

    attn_fused_kernel<<<BATCH * NCHUNK, THREADS>>>(
        hidden, enc, mask, attn_w, attn_b, out);
}